// round 10
// baseline (speedup 1.0000x reference)
#include <cuda_runtime.h>
#include <math.h>

#define VOCAB   1000000
#define DIM     128
#define BATCH   4096
#define NEG     5
#define LMAX    4
#define NROWS   40960            // BATCH * 2 * WINDOW
#define WPB     8                // warps per block
#define GRID    (NROWS / WPB)    // 5120 blocks

__device__ float    g_partials[GRID];
__device__ unsigned g_ticket = 0;

__device__ __forceinline__ float log_sigmoid(float x) {
    return fminf(x, 0.0f) - log1pf(__expf(-fabsf(x)));
}

__device__ __forceinline__ void add4(float4& a, const float4 b) {
    a.x += b.x; a.y += b.y; a.z += b.z; a.w += b.w;
}

__device__ __forceinline__ float dot4(const float4 a, const float4 b) {
    return a.x * b.x + a.y * b.y + a.z * b.z + a.w * b.w;
}

// exact reciprocal for len in {1,2,3,4}
__device__ __forceinline__ float inv_len(int l) {
    return (l == 1) ? 1.0f : (l == 2) ? 0.5f : (l == 3) ? (1.0f / 3.0f) : 0.25f;
}

__device__ __forceinline__ float4 grow(const float* __restrict__ t, int i, int col) {
    return __ldg(reinterpret_cast<const float4*>(t + (size_t)i * DIM + col));
}

// Ragged bag gather: up to 4 independent predicated 512B row loads.
__device__ __forceinline__ float4 bag_gather(const float* __restrict__ t,
                                             const int4 i4, const int len, const int col) {
    float4 acc = grow(t, i4.x, col);               // len >= 1 always
    if (len > 1) add4(acc, grow(t, i4.y, col));
    if (len > 2) add4(acc, grow(t, i4.z, col));
    if (len > 3) add4(acc, grow(t, i4.w, col));
    return acc;
}

__global__ void __launch_bounds__(256)
skipgram_kernel(const float* __restrict__ u_table,
                const float* __restrict__ v_table,
                const int*   __restrict__ pos_u_idx,
                const int*   __restrict__ pos_u_len,
                const int*   __restrict__ pos_v_idx,
                const int*   __restrict__ pos_v_len,
                const int*   __restrict__ neg_v_idx,
                const int*   __restrict__ neg_v_len,
                float* __restrict__ out) {
    const int wslot = threadIdx.x >> 5;
    const int row   = blockIdx.x * WPB + wslot;    // one warp per output row
    const int lane  = threadIdx.x & 31;
    const int col   = lane * 4;

    __shared__ float s_partial[WPB];
    __shared__ bool  s_last;

    // ---- positive pair: u and v, 8 independent 512B gathers ----
    const int  ulen = __ldg(pos_u_len + row);
    const int  vlen = __ldg(pos_v_len + row);
    const int4 ui   = __ldg(reinterpret_cast<const int4*>(pos_u_idx) + row);
    const int4 vi   = __ldg(reinterpret_cast<const int4*>(pos_v_idx) + row);

    float4 au = bag_gather(u_table, ui, ulen, col);
    float4 av = bag_gather(v_table, vi, vlen, col);

    const float inv_u = inv_len(ulen);
    float4 eu;
    eu.x = au.x * inv_u; eu.y = au.y * inv_u; eu.z = au.z * inv_u; eu.w = au.w * inv_u;

    float dpos = dot4(eu, av) * inv_len(vlen);
    #pragma unroll
    for (int off = 16; off > 0; off >>= 1)
        dpos += __shfl_xor_sync(0xFFFFFFFFu, dpos, off);
    float loss = log_sigmoid(dpos);

    const int4* nip = reinterpret_cast<const int4*>(neg_v_idx) + (size_t)row * NEG;
    const int*  nlp = neg_v_len + (size_t)row * NEG;

    // ---- negative pairs (0,1), (2,3): interleaved shuffle reductions ----
    #pragma unroll
    for (int p = 0; p < 2; ++p) {
        const int k = p * 2;
        const int  l0 = __ldg(nlp + k);
        const int  l1 = __ldg(nlp + k + 1);
        const int4 q0 = __ldg(nip + k);
        const int4 q1 = __ldg(nip + k + 1);

        float4 a0 = bag_gather(v_table, q0, l0, col);
        float4 a1 = bag_gather(v_table, q1, l1, col);

        float d0 = dot4(eu, a0) * inv_len(l0);
        float d1 = dot4(eu, a1) * inv_len(l1);
        #pragma unroll
        for (int off = 16; off > 0; off >>= 1) {
            d0 += __shfl_xor_sync(0xFFFFFFFFu, d0, off);
            d1 += __shfl_xor_sync(0xFFFFFFFFu, d1, off);
        }
        loss += log_sigmoid(-d0) + log_sigmoid(-d1);
    }

    // ---- last negative bag ----
    {
        const int  l4 = __ldg(nlp + 4);
        const int4 q4 = __ldg(nip + 4);
        float4 a4 = bag_gather(v_table, q4, l4, col);
        float d4 = dot4(eu, a4) * inv_len(l4);
        #pragma unroll
        for (int off = 16; off > 0; off >>= 1)
            d4 += __shfl_xor_sync(0xFFFFFFFFu, d4, off);
        loss += log_sigmoid(-d4);
    }

    if (lane == 0) s_partial[wslot] = -loss * (1.0f / (float)BATCH);
    __syncthreads();

    // ---- per-block partial -> scratch; last block reduces all partials ----
    if (threadIdx.x == 0) {
        float bsum = 0.f;
        #pragma unroll
        for (int i = 0; i < WPB; ++i) bsum += s_partial[i];
        g_partials[blockIdx.x] = bsum;
        __threadfence();
        const unsigned t = atomicInc(&g_ticket, GRID - 1);  // wraps to 0 at GRID-1
        s_last = (t == GRID - 1);
    }
    __syncthreads();

    if (s_last) {
        // all 256 threads of the final block reduce GRID partials
        float v = 0.f;
        for (int i = threadIdx.x; i < GRID; i += 256)
            v += g_partials[i];
        #pragma unroll
        for (int off = 16; off > 0; off >>= 1)
            v += __shfl_xor_sync(0xFFFFFFFFu, v, off);
        if (lane == 0) s_partial[wslot] = v;
        __syncthreads();
        if (threadIdx.x == 0) {
            float tot = 0.f;
            #pragma unroll
            for (int i = 0; i < WPB; ++i) tot += s_partial[i];
            out[0] = tot;          // plain store; no zero-init kernel needed
        }
    }
}

extern "C" void kernel_launch(void* const* d_in, const int* in_sizes, int n_in,
                              void* d_out, int out_size) {
    const float* u_table   = (const float*)d_in[0];
    const float* v_table   = (const float*)d_in[1];
    const int*   pos_u_idx = (const int*)d_in[2];
    const int*   pos_u_len = (const int*)d_in[3];
    const int*   pos_v_idx = (const int*)d_in[4];
    const int*   pos_v_len = (const int*)d_in[5];
    const int*   neg_v_idx = (const int*)d_in[6];
    const int*   neg_v_len = (const int*)d_in[7];
    float* out = (float*)d_out;

    skipgram_kernel<<<GRID, 256>>>(u_table, v_table,
                                   pos_u_idx, pos_u_len,
                                   pos_v_idx, pos_v_len,
                                   neg_v_idx, neg_v_len, out);
}

// round 11
// speedup vs baseline: 1.1633x; 1.1633x over previous
#include <cuda_runtime.h>
#include <math.h>

#define VOCAB   1000000
#define DIM     128
#define BATCH   4096
#define NEG     5
#define LMAX    4
#define NROWS   40960            // BATCH * 2 * WINDOW
#define WPB     8

__device__ __forceinline__ float log_sigmoid(float x) {
    return fminf(x, 0.0f) - log1pf(__expf(-fabsf(x)));
}

__device__ __forceinline__ void add4(float4& a, const float4 b) {
    a.x += b.x; a.y += b.y; a.z += b.z; a.w += b.w;
}

__device__ __forceinline__ float dot4(const float4 a, const float4 b) {
    return a.x * b.x + a.y * b.y + a.z * b.z + a.w * b.w;
}

// exact reciprocal for len in {1,2,3,4} (1/3 rounds once, same as ref divide)
__device__ __forceinline__ float inv_len(int l) {
    return (l == 1) ? 1.0f : (l == 2) ? 0.5f : (l == 3) ? (1.0f / 3.0f) : 0.25f;
}

__device__ __forceinline__ float4 grow(const float* __restrict__ t, int i, int col) {
    return __ldg(reinterpret_cast<const float4*>(t + (size_t)i * DIM + col));
}

// Ragged bag gather: up to 4 independent predicated 512B row loads.
__device__ __forceinline__ float4 bag_gather(const float* __restrict__ t,
                                             const int4 i4, const int len, const int col) {
    float4 acc = grow(t, i4.x, col);               // len >= 1 always
    if (len > 1) add4(acc, grow(t, i4.y, col));
    if (len > 2) add4(acc, grow(t, i4.z, col));
    if (len > 3) add4(acc, grow(t, i4.w, col));
    return acc;
}

__global__ void zero_out_kernel(float* out) { out[0] = 0.0f; }

__global__ void __launch_bounds__(256)
skipgram_kernel(const float* __restrict__ u_table,
                const float* __restrict__ v_table,
                const int*   __restrict__ pos_u_idx,
                const int*   __restrict__ pos_u_len,
                const int*   __restrict__ pos_v_idx,
                const int*   __restrict__ pos_v_len,
                const int*   __restrict__ neg_v_idx,
                const int*   __restrict__ neg_v_len,
                float* __restrict__ out) {
    const int wslot = threadIdx.x >> 5;
    const int row   = blockIdx.x * WPB + wslot;    // one warp per output row
    const int lane  = threadIdx.x & 31;
    const int col   = lane * 4;

    __shared__ float s_partial[WPB];

    // ---- positive pair: u and v, 8 independent 512B gathers ----
    const int  ulen = __ldg(pos_u_len + row);
    const int  vlen = __ldg(pos_v_len + row);
    const int4 ui   = __ldg(reinterpret_cast<const int4*>(pos_u_idx) + row);
    const int4 vi   = __ldg(reinterpret_cast<const int4*>(pos_v_idx) + row);

    float4 au = bag_gather(u_table, ui, ulen, col);
    float4 av = bag_gather(v_table, vi, vlen, col);

    const float inv_u = inv_len(ulen);
    float4 eu;
    eu.x = au.x * inv_u; eu.y = au.y * inv_u; eu.z = au.z * inv_u; eu.w = au.w * inv_u;

    float dpos = dot4(eu, av) * inv_len(vlen);
    #pragma unroll
    for (int off = 16; off > 0; off >>= 1)
        dpos += __shfl_xor_sync(0xFFFFFFFFu, dpos, off);
    float loss = log_sigmoid(dpos);

    const int4* nip = reinterpret_cast<const int4*>(neg_v_idx) + (size_t)row * NEG;
    const int*  nlp = neg_v_len + (size_t)row * NEG;

    // ---- negative pairs (0,1), (2,3): two bags' gathers in flight,
    //      reductions interleaved in one shuffle loop ----
    #pragma unroll
    for (int p = 0; p < 2; ++p) {
        const int k = p * 2;
        const int  l0 = __ldg(nlp + k);
        const int  l1 = __ldg(nlp + k + 1);
        const int4 q0 = __ldg(nip + k);
        const int4 q1 = __ldg(nip + k + 1);

        float4 a0 = bag_gather(v_table, q0, l0, col);
        float4 a1 = bag_gather(v_table, q1, l1, col);

        float d0 = dot4(eu, a0) * inv_len(l0);
        float d1 = dot4(eu, a1) * inv_len(l1);
        #pragma unroll
        for (int off = 16; off > 0; off >>= 1) {
            d0 += __shfl_xor_sync(0xFFFFFFFFu, d0, off);
            d1 += __shfl_xor_sync(0xFFFFFFFFu, d1, off);
        }
        loss += log_sigmoid(-d0) + log_sigmoid(-d1);
    }

    // ---- last negative bag ----
    {
        const int  l4 = __ldg(nlp + 4);
        const int4 q4 = __ldg(nip + 4);
        float4 a4 = bag_gather(v_table, q4, l4, col);
        float d4 = dot4(eu, a4) * inv_len(l4);
        #pragma unroll
        for (int off = 16; off > 0; off >>= 1)
            d4 += __shfl_xor_sync(0xFFFFFFFFu, d4, off);
        loss += log_sigmoid(-d4);
    }

    if (lane == 0) s_partial[wslot] = -loss * (1.0f / (float)BATCH);
    __syncthreads();

    if (threadIdx.x == 0) {
        float bsum = 0.f;
        #pragma unroll
        for (int i = 0; i < WPB; ++i) bsum += s_partial[i];
        atomicAdd(out, bsum);
    }
}

extern "C" void kernel_launch(void* const* d_in, const int* in_sizes, int n_in,
                              void* d_out, int out_size) {
    const float* u_table   = (const float*)d_in[0];
    const float* v_table   = (const float*)d_in[1];
    const int*   pos_u_idx = (const int*)d_in[2];
    const int*   pos_u_len = (const int*)d_in[3];
    const int*   pos_v_idx = (const int*)d_in[4];
    const int*   pos_v_len = (const int*)d_in[5];
    const int*   neg_v_idx = (const int*)d_in[6];
    const int*   neg_v_len = (const int*)d_in[7];
    float* out = (float*)d_out;

    zero_out_kernel<<<1, 1>>>(out);
    skipgram_kernel<<<NROWS / WPB, 256>>>(u_table, v_table,
                                          pos_u_idx, pos_u_len,
                                          pos_v_idx, pos_v_len,
                                          neg_v_idx, neg_v_len, out);
}

// round 12
// speedup vs baseline: 1.2711x; 1.0926x over previous
#include <cuda_runtime.h>
#include <math.h>

#define VOCAB   1000000
#define DIM     128
#define BATCH   4096
#define NEG     5
#define LMAX    4
#define NROWS   40960            // BATCH * 2 * WINDOW
#define WPB     8

__device__ __forceinline__ float log_sigmoid(float x) {
    return fminf(x, 0.0f) - log1pf(__expf(-fabsf(x)));
}

__device__ __forceinline__ void add4(float4& a, const float4 b) {
    a.x += b.x; a.y += b.y; a.z += b.z; a.w += b.w;
}

__device__ __forceinline__ float dot4(const float4 a, const float4 b) {
    return a.x * b.x + a.y * b.y + a.z * b.z + a.w * b.w;
}

__device__ __forceinline__ float4 grow(const float* __restrict__ t, int i, int col) {
    return __ldg(reinterpret_cast<const float4*>(t + (size_t)i * DIM + col));
}

// Ragged bag gather: up to 4 independent predicated 512B row loads.
__device__ __forceinline__ float4 bag_gather(const float* __restrict__ t,
                                             const int4 i4, const int len, const int col) {
    float4 acc = grow(t, i4.x, col);               // len >= 1 always
    if (len > 1) add4(acc, grow(t, i4.y, col));
    if (len > 2) add4(acc, grow(t, i4.z, col));
    if (len > 3) add4(acc, grow(t, i4.w, col));
    return acc;
}

__global__ void zero_out_kernel(float* out) { out[0] = 0.0f; }

__global__ void __launch_bounds__(256)
skipgram_kernel(const float* __restrict__ u_table,
                const float* __restrict__ v_table,
                const int*   __restrict__ pos_u_idx,
                const int*   __restrict__ pos_u_len,
                const int*   __restrict__ pos_v_idx,
                const int*   __restrict__ pos_v_len,
                const int*   __restrict__ neg_v_idx,
                const int*   __restrict__ neg_v_len,
                float* __restrict__ out) {
    const int wslot = threadIdx.x >> 5;
    const int row   = blockIdx.x * WPB + wslot;    // one warp per output row
    const int lane  = threadIdx.x & 31;
    const int col   = lane * 4;

    __shared__ float s_partial[WPB];

    // ---- positive pair: u and v, 8 independent 512B gathers in flight ----
    const int  ulen = __ldg(pos_u_len + row);
    const int  vlen = __ldg(pos_v_len + row);
    const int4 ui   = __ldg(reinterpret_cast<const int4*>(pos_u_idx) + row);   // warp-uniform
    const int4 vi   = __ldg(reinterpret_cast<const int4*>(pos_v_idx) + row);

    float4 au = bag_gather(u_table, ui, ulen, col);
    float4 av = bag_gather(v_table, vi, vlen, col);

    const float inv_u = 1.0f / (float)ulen;
    float4 eu;
    eu.x = au.x * inv_u; eu.y = au.y * inv_u; eu.z = au.z * inv_u; eu.w = au.w * inv_u;

    float dpos = dot4(eu, av) / (float)vlen;
    #pragma unroll
    for (int off = 16; off > 0; off >>= 1)
        dpos += __shfl_xor_sync(0xFFFFFFFFu, dpos, off);
    float loss = log_sigmoid(dpos);

    const int4* nip = reinterpret_cast<const int4*>(neg_v_idx) + (size_t)row * NEG;
    const int*  nlp = neg_v_len + (size_t)row * NEG;

    // ---- negative pairs: (0,1), (2,3): two bags' gathers in flight,
    //      reductions interleaved in one shuffle loop ----
    #pragma unroll
    for (int p = 0; p < 2; ++p) {
        const int k = p * 2;
        const int  l0 = __ldg(nlp + k);
        const int  l1 = __ldg(nlp + k + 1);
        const int4 q0 = __ldg(nip + k);
        const int4 q1 = __ldg(nip + k + 1);

        float4 a0 = bag_gather(v_table, q0, l0, col);
        float4 a1 = bag_gather(v_table, q1, l1, col);

        float d0 = dot4(eu, a0) / (float)l0;
        float d1 = dot4(eu, a1) / (float)l1;
        #pragma unroll
        for (int off = 16; off > 0; off >>= 1) {
            d0 += __shfl_xor_sync(0xFFFFFFFFu, d0, off);
            d1 += __shfl_xor_sync(0xFFFFFFFFu, d1, off);
        }
        loss += log_sigmoid(-d0) + log_sigmoid(-d1);
    }

    // ---- last negative bag ----
    {
        const int  l4 = __ldg(nlp + 4);
        const int4 q4 = __ldg(nip + 4);
        float4 a4 = bag_gather(v_table, q4, l4, col);
        float d4 = dot4(eu, a4) / (float)l4;
        #pragma unroll
        for (int off = 16; off > 0; off >>= 1)
            d4 += __shfl_xor_sync(0xFFFFFFFFu, d4, off);
        loss += log_sigmoid(-d4);
    }

    if (lane == 0) s_partial[wslot] = -loss * (1.0f / (float)BATCH);
    __syncthreads();

    if (threadIdx.x == 0) {
        float bsum = 0.f;
        #pragma unroll
        for (int i = 0; i < WPB; ++i) bsum += s_partial[i];
        atomicAdd(out, bsum);
    }
}

extern "C" void kernel_launch(void* const* d_in, const int* in_sizes, int n_in,
                              void* d_out, int out_size) {
    const float* u_table   = (const float*)d_in[0];
    const float* v_table   = (const float*)d_in[1];
    const int*   pos_u_idx = (const int*)d_in[2];
    const int*   pos_u_len = (const int*)d_in[3];
    const int*   pos_v_idx = (const int*)d_in[4];
    const int*   pos_v_len = (const int*)d_in[5];
    const int*   neg_v_idx = (const int*)d_in[6];
    const int*   neg_v_len = (const int*)d_in[7];
    float* out = (float*)d_out;

    zero_out_kernel<<<1, 1>>>(out);
    skipgram_kernel<<<NROWS / WPB, 256>>>(u_table, v_table,
                                          pos_u_idx, pos_u_len,
                                          pos_v_idx, pos_v_len,
                                          neg_v_idx, neg_v_len, out);
}

// round 13
// speedup vs baseline: 1.3029x; 1.0251x over previous
#include <cuda_runtime.h>
#include <math.h>

#define VOCAB   1000000
#define DIM     128
#define BATCH   4096
#define NEG     5
#define LMAX    4
#define NROWS   40960            // BATCH * 2 * WINDOW
#define WPB     8

__device__ __forceinline__ float log_sigmoid(float x) {
    return fminf(x, 0.0f) - log1pf(__expf(-fabsf(x)));
}

__device__ __forceinline__ void add4(float4& a, const float4 b) {
    a.x += b.x; a.y += b.y; a.z += b.z; a.w += b.w;
}

__device__ __forceinline__ float dot4(const float4 a, const float4 b) {
    return a.x * b.x + a.y * b.y + a.z * b.z + a.w * b.w;
}

__device__ __forceinline__ float4 grow(const float* __restrict__ t, int i, int col) {
    return __ldg(reinterpret_cast<const float4*>(t + (size_t)i * DIM + col));
}

// Ragged bag gather: up to 4 independent predicated 512B row loads.
__device__ __forceinline__ float4 bag_gather(const float* __restrict__ t,
                                             const int4 i4, const int len, const int col) {
    float4 acc = grow(t, i4.x, col);               // len >= 1 always
    if (len > 1) add4(acc, grow(t, i4.y, col));
    if (len > 2) add4(acc, grow(t, i4.z, col));
    if (len > 3) add4(acc, grow(t, i4.w, col));
    return acc;
}

__global__ void zero_out_kernel(float* out) { out[0] = 0.0f; }

__global__ void __launch_bounds__(256)
skipgram_kernel(const float* __restrict__ u_table,
                const float* __restrict__ v_table,
                const int*   __restrict__ pos_u_idx,
                const int*   __restrict__ pos_u_len,
                const int*   __restrict__ pos_v_idx,
                const int*   __restrict__ pos_v_len,
                const int*   __restrict__ neg_v_idx,
                const int*   __restrict__ neg_v_len,
                float* __restrict__ out) {
    const int wslot = threadIdx.x >> 5;
    const int row   = blockIdx.x * WPB + wslot;    // one warp per output row
    const int lane  = threadIdx.x & 31;
    const int col   = lane * 4;

    __shared__ float s_partial[WPB];

    // ---- positive pair: u and v, 8 independent 512B gathers in flight ----
    const int  ulen = __ldg(pos_u_len + row);
    const int  vlen = __ldg(pos_v_len + row);
    const int4 ui   = __ldg(reinterpret_cast<const int4*>(pos_u_idx) + row);   // warp-uniform
    const int4 vi   = __ldg(reinterpret_cast<const int4*>(pos_v_idx) + row);

    float4 au = bag_gather(u_table, ui, ulen, col);
    float4 av = bag_gather(v_table, vi, vlen, col);

    const float inv_u = __fdividef(1.0f, (float)ulen);
    float4 eu;
    eu.x = au.x * inv_u; eu.y = au.y * inv_u; eu.z = au.z * inv_u; eu.w = au.w * inv_u;

    float dpos = __fdividef(dot4(eu, av), (float)vlen);
    #pragma unroll
    for (int off = 16; off > 0; off >>= 1)
        dpos += __shfl_xor_sync(0xFFFFFFFFu, dpos, off);
    float loss = log_sigmoid(dpos);

    const int4* nip = reinterpret_cast<const int4*>(neg_v_idx) + (size_t)row * NEG;
    const int*  nlp = neg_v_len + (size_t)row * NEG;

    // ---- negative pairs: (0,1), (2,3): two bags' gathers in flight,
    //      reductions interleaved in one shuffle loop ----
    #pragma unroll
    for (int p = 0; p < 2; ++p) {
        const int k = p * 2;
        const int  l0 = __ldg(nlp + k);
        const int  l1 = __ldg(nlp + k + 1);
        const int4 q0 = __ldg(nip + k);
        const int4 q1 = __ldg(nip + k + 1);

        float4 a0 = bag_gather(v_table, q0, l0, col);
        float4 a1 = bag_gather(v_table, q1, l1, col);

        float d0 = __fdividef(dot4(eu, a0), (float)l0);
        float d1 = __fdividef(dot4(eu, a1), (float)l1);
        #pragma unroll
        for (int off = 16; off > 0; off >>= 1) {
            d0 += __shfl_xor_sync(0xFFFFFFFFu, d0, off);
            d1 += __shfl_xor_sync(0xFFFFFFFFu, d1, off);
        }
        loss += log_sigmoid(-d0) + log_sigmoid(-d1);
    }

    // ---- last negative bag ----
    {
        const int  l4 = __ldg(nlp + 4);
        const int4 q4 = __ldg(nip + 4);
        float4 a4 = bag_gather(v_table, q4, l4, col);
        float d4 = __fdividef(dot4(eu, a4), (float)l4);
        #pragma unroll
        for (int off = 16; off > 0; off >>= 1)
            d4 += __shfl_xor_sync(0xFFFFFFFFu, d4, off);
        loss += log_sigmoid(-d4);
    }

    if (lane == 0) s_partial[wslot] = -loss * (1.0f / (float)BATCH);
    __syncthreads();

    if (threadIdx.x == 0) {
        float bsum = 0.f;
        #pragma unroll
        for (int i = 0; i < WPB; ++i) bsum += s_partial[i];
        atomicAdd(out, bsum);
    }
}

extern "C" void kernel_launch(void* const* d_in, const int* in_sizes, int n_in,
                              void* d_out, int out_size) {
    const float* u_table   = (const float*)d_in[0];
    const float* v_table   = (const float*)d_in[1];
    const int*   pos_u_idx = (const int*)d_in[2];
    const int*   pos_u_len = (const int*)d_in[3];
    const int*   pos_v_idx = (const int*)d_in[4];
    const int*   pos_v_len = (const int*)d_in[5];
    const int*   neg_v_idx = (const int*)d_in[6];
    const int*   neg_v_len = (const int*)d_in[7];
    float* out = (float*)d_out;

    zero_out_kernel<<<1, 1>>>(out);
    skipgram_kernel<<<NROWS / WPB, 256>>>(u_table, v_table,
                                          pos_u_idx, pos_u_len,
                                          pos_v_idx, pos_v_len,
                                          neg_v_idx, neg_v_len, out);
}